// round 6
// baseline (speedup 1.0000x reference)
#include <cuda_runtime.h>

#define KMAX 21
#define GNUM 20     // reference always slices gt_instance[:20]
#define TILE 256
#define BT   672    // 21 warps: warp w owns plane k=w in phase 2
#define EPSF 1e-6f

// Global scratch (no allocation allowed)
__device__ float g_A[KMAX * GNUM];   // A[k*GNUM + g]
__device__ int   g_count;            // finalize ticket

__global__ void ms_init_kernel() {
    int t = threadIdx.x;
    if (t < KMAX * GNUM) g_A[t] = 0.0f;
    if (t == 0) g_count = 0;
}

// Fused accumulate + (last block) finalize.
// A[k,g] = sum_p d[p][k] * gt[g][p],  d = log(p+eps)-log(1-p+eps).
// argmin_g ce[k,g] == argmax_g A[k,g] (log(1-p) term constant over g).
__global__ __launch_bounds__(BT, 2) void ms_accum_kernel(
    const void* bufA, const void* bufB, int n, float* __restrict__ out)
{
    __shared__ __align__(16) float sd[TILE * KMAX];    // pixel-major d
    __shared__ __align__(16) unsigned int smask[TILE]; // 20-bit GT masks
    __shared__ int s_last;

    const int tid  = threadIdx.x;
    const int lane = tid & 31;
    const int wid  = tid >> 5;           // 0..20 == plane k in phase 2

    // ---- inline buffer-identity probe (per-warp, no sync needed) ----
    // gt_instance words are all {0,1}; segmentation floats in (0,1) have
    // large bit patterns. Every warp computes the same answer.
    const unsigned wA = ((const unsigned*)bufA)[lane];
    const unsigned wB = ((const unsigned*)bufB)[lane];
    const bool a_is_gt = (__ballot_sync(0xffffffffu, wA > 1u) == 0u);
    const bool b_is_gt = (__ballot_sync(0xffffffffu, wB > 1u) != 0u) ? false : true;
    const int sw = (a_is_gt && !b_is_gt) ? 1 : 0;  // 1: A=gt, B=seg
    const float* seg = (const float*)(sw ? bufB : bufA);  // (N, 21) f32
    const int*   gt  = (const int*)  (sw ? bufA : bufB);  // (21, N) {0,1}

    const int numTiles = (n + TILE - 1) / TILE;

    float acc[GNUM];
    #pragma unroll
    for (int g = 0; g < GNUM; g++) acc[g] = 0.0f;

    for (int tile = blockIdx.x; tile < numTiles; tile += gridDim.x) {
        const int base = tile * TILE;
        const int cnt = min(TILE, n - base);

        // ---- Phase 1a: coalesced seg load + log transform into smem ----
        if (cnt == TILE) {
            const float4* src = reinterpret_cast<const float4*>(
                seg + (long long)base * KMAX);
            float4* dst = reinterpret_cast<float4*>(sd);
            #pragma unroll
            for (int t = 0; t < 2; t++) {           // 1344 = 2*672
                int i = tid + t * BT;
                float4 v = __ldg(src + i);
                float4 o;
                o.x = __logf(v.x + EPSF) - __logf(1.0f - v.x + EPSF);
                o.y = __logf(v.y + EPSF) - __logf(1.0f - v.y + EPSF);
                o.z = __logf(v.z + EPSF) - __logf(1.0f - v.z + EPSF);
                o.w = __logf(v.w + EPSF) - __logf(1.0f - v.w + EPSF);
                dst[i] = o;
            }
        } else {
            const int total = cnt * KMAX;
            for (int i = tid; i < total; i += BT) {
                float p = __ldg(seg + (long long)base * KMAX + i);
                sd[i] = __logf(p + EPSF) - __logf(1.0f - p + EPSF);
            }
        }

        // ---- Phase 1b: 20-bit masks (first 8 warps, coalesced per plane) ----
        if (tid < TILE) {
            const int nidx = base + tid;
            unsigned m = 0;
            if (tid < cnt) {
                #pragma unroll
                for (int gg = 0; gg < GNUM; gg++) {
                    m |= (__ldg(gt + (long long)gg * n + nidx) != 0 ? 1u : 0u) << gg;
                }
            }
            smask[tid] = m;
        }
        __syncthreads();

        // ---- Phase 2: warp k, lane owns 8 pixels; 20 reg accumulators ----
        // LDS d: float index lane*21 + k + j*672 -> immediate offsets,
        // bank = (lane*21 + k) % 32, 21 coprime 32 -> conflict-free.
        if (cnt == TILE) {
            const int k = wid;
            const float* dbase = sd + lane * KMAX + k;
            #pragma unroll
            for (int j = 0; j < 8; j++) {
                const float d = dbase[j * 32 * KMAX];
                const unsigned m = smask[lane + j * 32];
                #pragma unroll
                for (int g = 0; g < GNUM; g++) {
                    if (m & (1u << g)) acc[g] += d;
                }
            }
        } else {
            const int k = wid;
            for (int p = lane; p < cnt; p += 32) {
                const float d = sd[p * KMAX + k];
                const unsigned m = smask[p];
                #pragma unroll
                for (int g = 0; g < GNUM; g++) {
                    if (m & (1u << g)) acc[g] += d;
                }
            }
        }
        __syncthreads();
    }

    // ---- Block reduction: butterfly per g, one atomic per (k,g) ----
    {
        const int k = wid;
        #pragma unroll
        for (int g = 0; g < GNUM; g++) {
            float v = acc[g];
            v += __shfl_xor_sync(0xffffffffu, v, 16);
            v += __shfl_xor_sync(0xffffffffu, v, 8);
            v += __shfl_xor_sync(0xffffffffu, v, 4);
            v += __shfl_xor_sync(0xffffffffu, v, 2);
            v += __shfl_xor_sync(0xffffffffu, v, 1);
            if (lane == 0) atomicAdd(&g_A[k * GNUM + g], v);
        }
    }

    // ---- Last block finalizes (ticket pattern) ----
    __threadfence();
    if (tid == 0) {
        s_last = (atomicAdd(&g_count, 1) == (int)gridDim.x - 1) ? 1 : 0;
    }
    __syncthreads();
    if (s_last && tid < KMAX) {
        const volatile float* A = g_A;
        float best = A[tid * GNUM + 0];
        int bi = 0;
        #pragma unroll
        for (int g = 1; g < GNUM; g++) {
            float v = A[tid * GNUM + g];
            if (v > best) { best = v; bi = g; }  // '>' keeps FIRST max == first min of ce
        }
        out[tid] = (float)bi;   // output buffer is compared as float32
    }
}

extern "C" void kernel_launch(void* const* d_in, const int* in_sizes, int n_in,
                              void* d_out, int out_size) {
    // The two LARGEST buffers are segmentation (N*21 f32) and gt_instance
    // (21*N i32); which is which is resolved on-device per-warp.
    int maxSize = 0;
    for (int i = 0; i < n_in; i++)
        if (in_sizes[i] > maxSize) maxSize = in_sizes[i];
    int idxA = -1, idxB = -1;
    for (int i = 0; i < n_in; i++) {
        if (in_sizes[i] == maxSize) {
            if (idxA < 0) idxA = i;
            else if (idxB < 0) idxB = i;
        }
    }
    if (idxB < 0) idxB = idxA;  // defensive

    const void* bufA = d_in[idxA];
    const void* bufB = d_in[idxB];
    const int n = maxSize / KMAX;   // pixels
    float* out = (float*)d_out;

    ms_init_kernel<<<1, 512>>>();

    const int numTiles = (n + TILE - 1) / TILE;
    int grid = 296;                 // 2 blocks/SM on 148 SMs
    if (grid > numTiles) grid = numTiles;
    ms_accum_kernel<<<grid, BT>>>(bufA, bufB, n, out);

    (void)out_size;
}